// round 1
// baseline (speedup 1.0000x reference)
#include <cuda_runtime.h>
#include <cuda_bf16.h>
#include <cstddef>

// ---------------------------------------------------------------------------
// Problem constants
// ---------------------------------------------------------------------------
#define N_NODES 50000
#define F_IN    768
#define PROJ    1024
#define HID     256
#define OUT_D   128
#define MAX_E   500000

// ---------------------------------------------------------------------------
// Static device scratch (no allocation allowed)
// ---------------------------------------------------------------------------
__device__ float g_A  [(size_t)N_NODES * 512];   // [a1 | a2]  = article_x @ Wfa + bfa
__device__ float g_C  [(size_t)N_NODES * 512];   // [c1 | cr3] = community_x @ Wcc + bcc
__device__ float g_h1 [(size_t)N_NODES * HID];
__device__ float g_M2 [(size_t)N_NODES * HID];
__device__ float g_h2 [(size_t)N_NODES * HID];
__device__ float g_g2 [(size_t)N_NODES * HID];
__device__ float g_h3 [(size_t)N_NODES * HID];
__device__ float g_Wfa[(size_t)F_IN * 512];      // [W1@Wl1 | W1@Wl2]
__device__ float g_Wcc[(size_t)F_IN * 512];      // [W2@Wr1 | Wr3]
__device__ float g_bfa[512];
__device__ float g_bcc[512];
__device__ int   g_rowptr[N_NODES + 1];
__device__ int   g_cnt[N_NODES];                 // histogram, then reused as fill cursor
__device__ int   g_col[MAX_E];

// ---------------------------------------------------------------------------
// SGEMM: C[M,N] = A[M,K] @ B[K,N] (+bias) (+D) (relu)
// 128x128 block tile, BK=8, 256 threads, 8x8 per-thread micro-tile.
// Requirements: N % 128 == 0, K % 8 == 0. M arbitrary (guarded).
// ---------------------------------------------------------------------------
#define BM 128
#define BN 128
#define BK 8
#define TM 8
#define TN 8

__global__ __launch_bounds__(256)
void sgemm_kernel(const float* __restrict__ A, int lda,
                  const float* __restrict__ B, int ldb,
                  float* __restrict__ C, int ldc,
                  const float* __restrict__ bias,
                  const float* __restrict__ D, int ldd,
                  int M, int N, int K, int relu)
{
    __shared__ float As[BK][BM];
    __shared__ float Bs[BK][BN];

    const int tid = threadIdx.x;
    const int tx = tid & 15;        // 0..15  -> column group
    const int ty = tid >> 4;        // 0..15  -> row group
    const int row0 = blockIdx.y * BM;
    const int col0 = blockIdx.x * BN;

    // A tile load mapping: 128 rows x 8 k, one float4 per thread
    const int aRow = tid >> 1;            // 0..127
    const int aK   = (tid & 1) * 4;       // 0 or 4
    // B tile load mapping: 8 k x 128 cols, one float4 per thread
    const int bK   = tid >> 5;            // 0..7
    const int bCol = (tid & 31) * 4;      // 0..124

    const bool aValid = (row0 + aRow) < M;
    const float* Aptr = A + (size_t)(row0 + aRow) * lda + aK;
    const float* Bptr = B + (size_t)bK * ldb + col0 + bCol;

    float acc[TM][TN];
#pragma unroll
    for (int i = 0; i < TM; i++)
#pragma unroll
        for (int j = 0; j < TN; j++) acc[i][j] = 0.f;

    for (int k0 = 0; k0 < K; k0 += BK) {
        float4 av = aValid ? *(const float4*)Aptr : make_float4(0.f, 0.f, 0.f, 0.f);
        float4 bv = *(const float4*)Bptr;
        Aptr += BK;
        Bptr += (size_t)BK * ldb;

        As[aK + 0][aRow] = av.x;
        As[aK + 1][aRow] = av.y;
        As[aK + 2][aRow] = av.z;
        As[aK + 3][aRow] = av.w;
        *(float4*)&Bs[bK][bCol] = bv;
        __syncthreads();

#pragma unroll
        for (int kk = 0; kk < BK; kk++) {
            float ra[TM], rb[TN];
#pragma unroll
            for (int i = 0; i < TM; i++) ra[i] = As[kk][ty * TM + i];
#pragma unroll
            for (int j = 0; j < TN; j++) rb[j] = Bs[kk][tx * TN + j];
#pragma unroll
            for (int i = 0; i < TM; i++)
#pragma unroll
                for (int j = 0; j < TN; j++) acc[i][j] += ra[i] * rb[j];
        }
        __syncthreads();
    }

    // Epilogue
#pragma unroll
    for (int i = 0; i < TM; i++) {
        int r = row0 + ty * TM + i;
        if (r >= M) break;
#pragma unroll
        for (int j = 0; j < TN; j += 4) {
            int c = col0 + tx * TN + j;
            float4 v = make_float4(acc[i][j], acc[i][j + 1], acc[i][j + 2], acc[i][j + 3]);
            if (bias) {
                v.x += bias[c]; v.y += bias[c + 1]; v.z += bias[c + 2]; v.w += bias[c + 3];
            }
            if (D) {
                float4 d = *(const float4*)&D[(size_t)r * ldd + c];
                v.x += d.x; v.y += d.y; v.z += d.z; v.w += d.w;
            }
            if (relu) {
                v.x = fmaxf(v.x, 0.f); v.y = fmaxf(v.y, 0.f);
                v.z = fmaxf(v.z, 0.f); v.w = fmaxf(v.w, 0.f);
            }
            *(float4*)&C[(size_t)r * ldc + c] = v;
        }
    }
}

// ---------------------------------------------------------------------------
// Weight/bias fusion helpers
// ---------------------------------------------------------------------------
__global__ void copy_wr3_kernel(const float* __restrict__ Wr3, float* __restrict__ Wcc)
{
    int i = blockIdx.x * blockDim.x + threadIdx.x;
    if (i < F_IN * HID) {
        int r = i / HID, c = i % HID;
        Wcc[(size_t)r * 512 + 256 + c] = Wr3[i];
    }
}

__global__ void fuse_bias_kernel(const float* __restrict__ b1,
                                 const float* __restrict__ Wl1,
                                 const float* __restrict__ Wl2,
                                 const float* __restrict__ b2,
                                 const float* __restrict__ Wr1,
                                 const float* __restrict__ bl1,
                                 const float* __restrict__ bl3,
                                 float* __restrict__ bfa,
                                 float* __restrict__ bcc)
{
    int j = threadIdx.x;   // 0..255
    if (j < HID) {
        float s1 = 0.f, s2 = 0.f, s3 = 0.f;
        for (int k = 0; k < PROJ; k++) {
            float b1k = b1[k];
            s1 += b1k * Wl1[(size_t)k * HID + j];
            s2 += b1k * Wl2[(size_t)k * HID + j];
            s3 += b2[k] * Wr1[(size_t)k * HID + j];
        }
        bfa[j]       = s1;
        bfa[256 + j] = s2;
        bcc[j]       = s3 + bl1[j];
        bcc[256 + j] = bl3[j];
    }
}

// ---------------------------------------------------------------------------
// CSR build: histogram -> exclusive scan -> cursor fill
// ---------------------------------------------------------------------------
__global__ void hist_kernel(const int* __restrict__ dst, int E, int* __restrict__ cnt)
{
    int e = blockIdx.x * blockDim.x + threadIdx.x;
    if (e < E) atomicAdd(&cnt[dst[e]], 1);
}

__global__ void exscan_kernel(const int* __restrict__ cnt, int* __restrict__ rowptr, int n)
{
    __shared__ int buf[1024];
    __shared__ int carry_s;
    int tid = threadIdx.x;
    if (tid == 0) carry_s = 0;
    __syncthreads();
    for (int base = 0; base < n; base += 1024) {
        int idx = base + tid;
        int v = (idx < n) ? cnt[idx] : 0;
        buf[tid] = v;
        __syncthreads();
        for (int off = 1; off < 1024; off <<= 1) {
            int t = (tid >= off) ? buf[tid - off] : 0;
            __syncthreads();
            buf[tid] += t;
            __syncthreads();
        }
        int carry = carry_s;
        if (idx < n) rowptr[idx] = carry + buf[tid] - v;
        __syncthreads();
        if (tid == 1023) carry_s = carry + buf[1023];
        __syncthreads();
    }
    if (tid == 0) rowptr[n] = carry_s;
}

__global__ void copy_cursor_kernel(const int* __restrict__ rowptr, int* __restrict__ cur, int n)
{
    int i = blockIdx.x * blockDim.x + threadIdx.x;
    if (i < n) cur[i] = rowptr[i];
}

__global__ void fill_kernel(const int* __restrict__ src, const int* __restrict__ dst,
                            int E, int* __restrict__ cur, int* __restrict__ col)
{
    int e = blockIdx.x * blockDim.x + threadIdx.x;
    if (e < E) {
        int p = atomicAdd(&cur[dst[e]], 1);
        col[p] = src[e];
    }
}

// ---------------------------------------------------------------------------
// CSR mean-aggregate over 256-dim features, with optional add matrix + relu.
// One block (256 threads) per destination node; thread j owns feature j.
// ---------------------------------------------------------------------------
__global__ __launch_bounds__(256)
void csr_mean_kernel(const int* __restrict__ rowptr, const int* __restrict__ col,
                     const float* __restrict__ feat, int ldf,
                     const float* __restrict__ add, int ldadd,
                     float* __restrict__ out, int relu)
{
    int node = blockIdx.x;
    int j = threadIdx.x;
    int s = rowptr[node];
    int e = rowptr[node + 1];

    float acc = 0.f;
    int k = s;
    // unrolled by 4 for MLP
    for (; k + 4 <= e; k += 4) {
        int c0 = col[k], c1 = col[k + 1], c2 = col[k + 2], c3 = col[k + 3];
        float v0 = feat[(size_t)c0 * ldf + j];
        float v1 = feat[(size_t)c1 * ldf + j];
        float v2 = feat[(size_t)c2 * ldf + j];
        float v3 = feat[(size_t)c3 * ldf + j];
        acc += (v0 + v1) + (v2 + v3);
    }
    for (; k < e; k++) acc += feat[(size_t)col[k] * ldf + j];

    float m = acc / fmaxf((float)(e - s), 1.f);
    if (add) m += add[(size_t)node * ldadd + j];
    if (relu) m = fmaxf(m, 0.f);
    out[(size_t)node * HID + j] = m;
}

// ---------------------------------------------------------------------------
// Host orchestration
// ---------------------------------------------------------------------------
static inline void launch_sgemm(const float* A, int lda, const float* B, int ldb,
                                float* C, int ldc, const float* bias,
                                const float* D, int ldd, int M, int N, int K, int relu)
{
    dim3 grid(N / BN, (M + BM - 1) / BM);
    sgemm_kernel<<<grid, 256>>>(A, lda, B, ldb, C, ldc, bias, D, ldd, M, N, K, relu);
}

static void build_csr(const int* edges, int E, int* rowptr, int* cnt, int* col)
{
    const int* src = edges;
    const int* dst = edges + E;
    cudaMemsetAsync(cnt, 0, N_NODES * sizeof(int));
    hist_kernel<<<(E + 255) / 256, 256>>>(dst, E, cnt);
    exscan_kernel<<<1, 1024>>>(cnt, rowptr, N_NODES);
    copy_cursor_kernel<<<(N_NODES + 255) / 256, 256>>>(rowptr, cnt, N_NODES);
    fill_kernel<<<(E + 255) / 256, 256>>>(src, dst, E, cnt, col);
}

extern "C" void kernel_launch(void* const* d_in, const int* in_sizes, int n_in,
                              void* d_out, int out_size)
{
    const float* article_x   = (const float*)d_in[0];
    const float* community_x = (const float*)d_in[1];
    const int*   e_wb = (const int*)d_in[2];
    const int*   e_mb = (const int*)d_in[3];
    const int*   e_int = (const int*)d_in[4];
    const float* W1  = (const float*)d_in[5];
    const float* b1  = (const float*)d_in[6];
    const float* W2  = (const float*)d_in[7];
    const float* b2  = (const float*)d_in[8];
    const float* Wl1 = (const float*)d_in[9];
    const float* bl1 = (const float*)d_in[10];
    const float* Wr1 = (const float*)d_in[11];
    const float* Wl2 = (const float*)d_in[12];
    const float* bl2 = (const float*)d_in[13];
    const float* Wr2 = (const float*)d_in[14];
    const float* Wl3 = (const float*)d_in[15];
    const float* bl3 = (const float*)d_in[16];
    const float* Wr3 = (const float*)d_in[17];
    const float* W3  = (const float*)d_in[18];
    const float* b3  = (const float*)d_in[19];

    const int E_wb  = in_sizes[2] / 2;
    const int E_mb  = in_sizes[3] / 2;
    const int E_int = in_sizes[4] / 2;

    float *A, *C, *h1, *M2, *h2, *g2, *h3, *Wfa, *Wcc, *bfa, *bcc;
    int *rowptr, *cnt, *col;
    cudaGetSymbolAddress((void**)&A,   g_A);
    cudaGetSymbolAddress((void**)&C,   g_C);
    cudaGetSymbolAddress((void**)&h1,  g_h1);
    cudaGetSymbolAddress((void**)&M2,  g_M2);
    cudaGetSymbolAddress((void**)&h2,  g_h2);
    cudaGetSymbolAddress((void**)&g2,  g_g2);
    cudaGetSymbolAddress((void**)&h3,  g_h3);
    cudaGetSymbolAddress((void**)&Wfa, g_Wfa);
    cudaGetSymbolAddress((void**)&Wcc, g_Wcc);
    cudaGetSymbolAddress((void**)&bfa, g_bfa);
    cudaGetSymbolAddress((void**)&bcc, g_bcc);
    cudaGetSymbolAddress((void**)&rowptr, g_rowptr);
    cudaGetSymbolAddress((void**)&cnt,    g_cnt);
    cudaGetSymbolAddress((void**)&col,    g_col);

    // --- 1. fold weights -------------------------------------------------
    // Wfa[:, :256] = W1 @ Wl1 ; Wfa[:, 256:] = W1 @ Wl2
    launch_sgemm(W1, PROJ, Wl1, HID, Wfa,       512, nullptr, nullptr, 0, F_IN, HID, PROJ, 0);
    launch_sgemm(W1, PROJ, Wl2, HID, Wfa + 256, 512, nullptr, nullptr, 0, F_IN, HID, PROJ, 0);
    // Wcc[:, :256] = W2 @ Wr1 ; Wcc[:, 256:] = Wr3 (copy)
    launch_sgemm(W2, PROJ, Wr1, HID, Wcc,       512, nullptr, nullptr, 0, F_IN, HID, PROJ, 0);
    copy_wr3_kernel<<<(F_IN * HID + 255) / 256, 256>>>(Wr3, Wcc);
    fuse_bias_kernel<<<1, 256>>>(b1, Wl1, Wl2, b2, Wr1, bl1, bl3, bfa, bcc);

    // --- 2. big projections ---------------------------------------------
    // A = article_x @ Wfa + bfa        ->  [a1 | a2]
    launch_sgemm(article_x,   F_IN, Wfa, 512, A, 512, bfa, nullptr, 0, N_NODES, 512, F_IN, 0);
    // C = community_x @ Wcc + bcc      ->  [c1 (incl. bl1) | cr3 (incl. bl3)]
    launch_sgemm(community_x, F_IN, Wcc, 512, C, 512, bcc, nullptr, 0, N_NODES, 512, F_IN, 0);

    // --- 3. conv1: h1 = relu(mean_wb(a1) + c1) ---------------------------
    build_csr(e_wb, E_wb, rowptr, cnt, col);
    csr_mean_kernel<<<N_NODES, 256>>>(rowptr, col, A, 512, C, 512, h1, 1);

    // --- 4. conv2: h2 = relu(mean_mb(a2) + h1 @ Wr2 + bl2) ---------------
    build_csr(e_mb, E_mb, rowptr, cnt, col);
    csr_mean_kernel<<<N_NODES, 256>>>(rowptr, col, A + 256, 512, nullptr, 0, M2, 0);
    launch_sgemm(h1, HID, Wr2, HID, h2, HID, bl2, M2, HID, N_NODES, HID, HID, 1);

    // --- 5. conv3: h3 = relu(mean_int(h2 @ Wl3) + cr3) -------------------
    launch_sgemm(h2, HID, Wl3, HID, g2, HID, nullptr, nullptr, 0, N_NODES, HID, HID, 0);
    build_csr(e_int, E_int, rowptr, cnt, col);
    csr_mean_kernel<<<N_NODES, 256>>>(rowptr, col, g2, HID, C + 256, 512, h3, 1);

    // --- 6. out = h3 @ W3 + b3 -------------------------------------------
    launch_sgemm(h3, HID, W3, OUT_D, (float*)d_out, OUT_D, b3, nullptr, 0, N_NODES, OUT_D, HID, 0);
}

// round 4
// speedup vs baseline: 2.0492x; 2.0492x over previous
#include <cuda_runtime.h>
#include <cstddef>
#include <cstdint>

// ---------------------------------------------------------------------------
// Problem constants
// ---------------------------------------------------------------------------
#define N_NODES 50000
#define F_IN    768
#define PROJ    1024
#define HID     256
#define OUT_D   128
#define MAXE    500000

// ---------------------------------------------------------------------------
// Static device scratch
// ---------------------------------------------------------------------------
__device__ float g_A1 [(size_t)N_NODES * HID];
__device__ float g_A2 [(size_t)N_NODES * HID];
__device__ float g_C1 [(size_t)N_NODES * HID];
__device__ float g_CR3[(size_t)N_NODES * HID];
__device__ float g_h1 [(size_t)N_NODES * HID];
__device__ float g_M2 [(size_t)N_NODES * HID];
__device__ float g_h2 [(size_t)N_NODES * HID];
__device__ float g_g2 [(size_t)N_NODES * HID];
__device__ float g_h3 [(size_t)N_NODES * HID];
__device__ float g_Wfa  [(size_t)F_IN * 512];   // [W1@Wl1 | W1@Wl2]
__device__ float g_Wcc  [(size_t)F_IN * 512];   // [W2@Wr1 | Wr3]
__device__ float g_Wfa_t[(size_t)512 * F_IN];   // transposed, tf32-rounded
__device__ float g_Wcc_t[(size_t)512 * F_IN];
__device__ float g_Wr2_t[(size_t)HID * HID];
__device__ float g_Wl3_t[(size_t)HID * HID];
__device__ float g_W3_t [(size_t)OUT_D * HID];
__device__ float g_bfa[512];
__device__ float g_bcc[512];
__device__ int g_rp0[N_NODES + 1], g_rp1[N_NODES + 1], g_rp2[N_NODES + 1];
__device__ int g_cnt[N_NODES];
__device__ int g_col0[MAXE], g_col1[MAXE], g_col2[MAXE];

// ---------------------------------------------------------------------------
// tf32 helpers
// ---------------------------------------------------------------------------
__device__ __forceinline__ uint32_t f2tf32(float f) {
    uint32_t u;
    asm("cvt.rna.tf32.f32 %0, %1;" : "=r"(u) : "f"(f));
    return u;
}

__device__ __forceinline__ void mma_tf32(float* c, const uint32_t* a, const uint32_t* b) {
    asm volatile(
        "mma.sync.aligned.m16n8k8.row.col.f32.tf32.tf32.f32 "
        "{%0,%1,%2,%3}, {%4,%5,%6,%7}, {%8,%9}, {%0,%1,%2,%3};"
        : "+f"(c[0]), "+f"(c[1]), "+f"(c[2]), "+f"(c[3])
        : "r"(a[0]), "r"(a[1]), "r"(a[2]), "r"(a[3]), "r"(b[0]), "r"(b[1]));
}

__device__ __forceinline__ void cp16(uint32_t dst, const void* src) {
    asm volatile("cp.async.cg.shared.global [%0], [%1], 16;\n" :: "r"(dst), "l"(src));
}

// ---------------------------------------------------------------------------
// tf32 tensor-core GEMM: C[M,N] = A[M,K] @ Bt[N,K]^T (+bias)(+D)(relu)
// Bt is pre-transposed [N][K] with tf32-rounded values stored as float bits.
// BM=128 BN=128 BK=32, 256 threads, 8 warps (4x2), warp tile 32x64.
// Optional column-split output: cols >= splitcol go to C2 at (col - splitcol).
// Requires N%128==0, K%32==0, lda%4==0.
// ---------------------------------------------------------------------------
#define TBM 128
#define TBN 128
#define TBK 32
#define TPAD 36
#define STAGE_F (TBM * TPAD + TBN * TPAD)   // floats per stage

__global__ __launch_bounds__(256, 2)
void tf32_gemm_kernel(const float* __restrict__ A, int lda,
                      const float* __restrict__ Bt, int ldb,
                      float* __restrict__ C, int ldc,
                      float* __restrict__ C2, int splitcol, int ldc2,
                      const float* __restrict__ bias,
                      const float* __restrict__ D, int ldd,
                      int M, int N, int K, int relu)
{
    extern __shared__ float sm[];
    const int tid  = threadIdx.x;
    const int lane = tid & 31;
    const int wid  = tid >> 5;
    const int wm   = wid >> 1;     // 0..3
    const int wn   = wid & 1;      // 0..1
    const int row0 = blockIdx.y * TBM;
    const int col0 = blockIdx.x * TBN;

    // cp.async mapping: 4 float4 per thread per tile (128x32 floats)
    const int ar0 = tid >> 3;              // 0..31
    const int akv = (tid & 7) * 4;         // 0,4,..28

    const float* aP[4];
    const float* bP[4];
    uint32_t sA[4], sB[4];
    uint32_t smem_base = (uint32_t)__cvta_generic_to_shared(sm);
#pragma unroll
    for (int t = 0; t < 4; t++) {
        int r = row0 + ar0 + 32 * t;
        if (r > M - 1) r = M - 1;                      // clamp (rows >= M discarded)
        aP[t] = A + (size_t)r * lda + akv;
        bP[t] = Bt + (size_t)(col0 + ar0 + 32 * t) * ldb + akv;
        sA[t] = smem_base + (uint32_t)(((ar0 + 32 * t) * TPAD + akv) * 4);
        sB[t] = smem_base + (uint32_t)((TBM * TPAD + (ar0 + 32 * t) * TPAD + akv) * 4);
    }

    float acc[2][8][4];
#pragma unroll
    for (int i = 0; i < 2; i++)
#pragma unroll
        for (int j = 0; j < 8; j++)
#pragma unroll
            for (int q = 0; q < 4; q++) acc[i][j][q] = 0.f;

    const int KT = K / TBK;

    // prologue: stage 0
#pragma unroll
    for (int t = 0; t < 4; t++) { cp16(sA[t], aP[t]); cp16(sB[t], bP[t]); }
    asm volatile("cp.async.commit_group;\n" ::);
    asm volatile("cp.async.wait_group 0;\n" ::);
    __syncthreads();

    const int arow = wm * 32 + (lane >> 2);
    const int acol = lane & 3;

    for (int kt = 0; kt < KT; kt++) {
        const int s = kt & 1;
        if (kt + 1 < KT) {
            const int k0 = (kt + 1) * TBK;
            const uint32_t so = (uint32_t)((s ^ 1) * STAGE_F * 4);
#pragma unroll
            for (int t = 0; t < 4; t++) {
                cp16(sA[t] + so, aP[t] + k0);
                cp16(sB[t] + so, bP[t] + k0);
            }
            asm volatile("cp.async.commit_group;\n" ::);
        }

        const int sb = s * STAGE_F;
#pragma unroll
        for (int kk = 0; kk < 4; kk++) {
            const int kb = kk * 8;
            uint32_t a[2][4], b[8][2];
#pragma unroll
            for (int mt = 0; mt < 2; mt++) {
                int r = sb + (arow + mt * 16) * TPAD + kb + acol;
                a[mt][0] = f2tf32(sm[r]);
                a[mt][1] = f2tf32(sm[r + 8 * TPAD]);
                a[mt][2] = f2tf32(sm[r + 4]);
                a[mt][3] = f2tf32(sm[r + 8 * TPAD + 4]);
            }
#pragma unroll
            for (int nt = 0; nt < 8; nt++) {
                int nrow = wn * 64 + nt * 8 + (lane >> 2);
                int off = sb + TBM * TPAD + nrow * TPAD + kb + acol;
                b[nt][0] = __float_as_uint(sm[off]);
                b[nt][1] = __float_as_uint(sm[off + 4]);
            }
#pragma unroll
            for (int mt = 0; mt < 2; mt++)
#pragma unroll
                for (int nt = 0; nt < 8; nt++)
                    mma_tf32(acc[mt][nt], a[mt], b[nt]);
        }

        if (kt + 1 < KT) {
            asm volatile("cp.async.wait_group 0;\n" ::);
            __syncthreads();
        }
    }

    // epilogue
#pragma unroll
    for (int mt = 0; mt < 2; mt++) {
#pragma unroll
        for (int half = 0; half < 2; half++) {
            int r = row0 + wm * 32 + mt * 16 + (lane >> 2) + half * 8;
            if (r >= M) continue;
#pragma unroll
            for (int nt = 0; nt < 8; nt++) {
                int c = col0 + wn * 64 + nt * 8 + (lane & 3) * 2;
                float v0 = acc[mt][nt][half * 2 + 0];
                float v1 = acc[mt][nt][half * 2 + 1];
                if (bias) { v0 += bias[c]; v1 += bias[c + 1]; }
                if (D) {
                    float2 d = *(const float2*)&D[(size_t)r * ldd + c];
                    v0 += d.x; v1 += d.y;
                }
                if (relu) { v0 = fmaxf(v0, 0.f); v1 = fmaxf(v1, 0.f); }
                float2 o = make_float2(v0, v1);
                if (c >= splitcol)
                    *(float2*)&C2[(size_t)r * ldc2 + (c - splitcol)] = o;
                else
                    *(float2*)&C[(size_t)r * ldc + c] = o;
            }
        }
    }
}

// ---------------------------------------------------------------------------
// fp32 SGEMM (weight-fold only; exact). 128x128x8, 256 thr, 8x8 per thread.
// ---------------------------------------------------------------------------
#define BM 128
#define BN 128
#define BKF 8
#define TM 8
#define TN 8

__global__ __launch_bounds__(256)
void sgemm_kernel(const float* __restrict__ A, int lda,
                  const float* __restrict__ B, int ldb,
                  float* __restrict__ C, int ldc,
                  int M, int N, int K)
{
    __shared__ float As[BKF][BM];
    __shared__ float Bs[BKF][BN];
    const int tid = threadIdx.x;
    const int tx = tid & 15, ty = tid >> 4;
    const int row0 = blockIdx.y * BM, col0 = blockIdx.x * BN;
    const int aRow = tid >> 1, aK = (tid & 1) * 4;
    const int bK = tid >> 5, bCol = (tid & 31) * 4;
    const bool aValid = (row0 + aRow) < M;
    const float* Aptr = A + (size_t)(row0 + aRow) * lda + aK;
    const float* Bptr = B + (size_t)bK * ldb + col0 + bCol;

    float acc[TM][TN];
#pragma unroll
    for (int i = 0; i < TM; i++)
#pragma unroll
        for (int j = 0; j < TN; j++) acc[i][j] = 0.f;

    for (int k0 = 0; k0 < K; k0 += BKF) {
        float4 av = aValid ? *(const float4*)Aptr : make_float4(0, 0, 0, 0);
        float4 bv = *(const float4*)Bptr;
        Aptr += BKF; Bptr += (size_t)BKF * ldb;
        As[aK + 0][aRow] = av.x; As[aK + 1][aRow] = av.y;
        As[aK + 2][aRow] = av.z; As[aK + 3][aRow] = av.w;
        *(float4*)&Bs[bK][bCol] = bv;
        __syncthreads();
#pragma unroll
        for (int kk = 0; kk < BKF; kk++) {
            float ra[TM], rb[TN];
#pragma unroll
            for (int i = 0; i < TM; i++) ra[i] = As[kk][ty * TM + i];
#pragma unroll
            for (int j = 0; j < TN; j++) rb[j] = Bs[kk][tx * TN + j];
#pragma unroll
            for (int i = 0; i < TM; i++)
#pragma unroll
                for (int j = 0; j < TN; j++) acc[i][j] += ra[i] * rb[j];
        }
        __syncthreads();
    }
#pragma unroll
    for (int i = 0; i < TM; i++) {
        int r = row0 + ty * TM + i;
        if (r >= M) break;
#pragma unroll
        for (int j = 0; j < TN; j += 4) {
            int c = col0 + tx * TN + j;
            *(float4*)&C[(size_t)r * ldc + c] =
                make_float4(acc[i][j], acc[i][j + 1], acc[i][j + 2], acc[i][j + 3]);
        }
    }
}

// ---------------------------------------------------------------------------
// Transpose + tf32-round: out[C_][R] = tf32(in[R][C_]^T)
// ---------------------------------------------------------------------------
__global__ void transpose_cvt_kernel(const float* __restrict__ in, int R, int C_,
                                     float* __restrict__ out)
{
    __shared__ float t[32][33];
    int bx = blockIdx.x * 32, by = blockIdx.y * 32;
#pragma unroll
    for (int i = 0; i < 32; i += 8) {
        int y = by + threadIdx.y + i, x = bx + threadIdx.x;
        if (y < R && x < C_) t[threadIdx.y + i][threadIdx.x] = in[(size_t)y * C_ + x];
    }
    __syncthreads();
#pragma unroll
    for (int i = 0; i < 32; i += 8) {
        int oy = bx + threadIdx.y + i, ox = by + threadIdx.x;
        if (oy < C_ && ox < R)
            out[(size_t)oy * R + ox] = __uint_as_float(f2tf32(t[threadIdx.x][threadIdx.y + i]));
    }
}

// ---------------------------------------------------------------------------
// Weight/bias fusion
// ---------------------------------------------------------------------------
__global__ void copy_wr3_kernel(const float* __restrict__ Wr3, float* __restrict__ Wcc)
{
    int i = blockIdx.x * blockDim.x + threadIdx.x;
    if (i < F_IN * HID) {
        int r = i / HID, c = i % HID;
        Wcc[(size_t)r * 512 + 256 + c] = Wr3[i];
    }
}

__global__ void fuse_bias_kernel(const float* __restrict__ b1,
                                 const float* __restrict__ Wl1,
                                 const float* __restrict__ Wl2,
                                 const float* __restrict__ b2,
                                 const float* __restrict__ Wr1,
                                 const float* __restrict__ bl1,
                                 const float* __restrict__ bl3,
                                 float* __restrict__ bfa,
                                 float* __restrict__ bcc)
{
    int j = threadIdx.x;
    if (j < HID) {
        float s1 = 0.f, s2 = 0.f, s3 = 0.f;
        for (int k = 0; k < PROJ; k++) {
            float b1k = b1[k];
            s1 += b1k * Wl1[(size_t)k * HID + j];
            s2 += b1k * Wl2[(size_t)k * HID + j];
            s3 += b2[k] * Wr1[(size_t)k * HID + j];
        }
        bfa[j] = s1;
        bfa[256 + j] = s2;
        bcc[j] = s3 + bl1[j];
        bcc[256 + j] = bl3[j];
    }
}

// ---------------------------------------------------------------------------
// CSR build
// ---------------------------------------------------------------------------
__global__ void hist_kernel(const int* __restrict__ dst, int E, int* __restrict__ cnt)
{
    int e = blockIdx.x * blockDim.x + threadIdx.x;
    if (e < E) atomicAdd(&cnt[dst[e]], 1);
}

__global__ void exscan_kernel(const int* __restrict__ cnt, int* __restrict__ rowptr, int n)
{
    __shared__ int wsum[32];
    __shared__ int carry;
    int tid = threadIdx.x, lane = tid & 31, warp = tid >> 5;
    if (tid == 0) carry = 0;
    __syncthreads();
    for (int base = 0; base < n; base += 1024) {
        int idx = base + tid;
        int v = (idx < n) ? cnt[idx] : 0;
        int s = v;
#pragma unroll
        for (int off = 1; off < 32; off <<= 1) {
            int t = __shfl_up_sync(0xffffffffu, s, off);
            if (lane >= off) s += t;
        }
        if (lane == 31) wsum[warp] = s;
        __syncthreads();
        if (warp == 0) {
            int w = wsum[lane];
#pragma unroll
            for (int off = 1; off < 32; off <<= 1) {
                int t = __shfl_up_sync(0xffffffffu, w, off);
                if (lane >= off) w += t;
            }
            wsum[lane] = w;
        }
        __syncthreads();
        int woff = warp ? wsum[warp - 1] : 0;
        int myc = carry;
        int total = wsum[31];
        if (idx < n) rowptr[idx] = myc + woff + s - v;
        __syncthreads();
        if (tid == 0) carry = myc + total;
        __syncthreads();
    }
    if (tid == 0) rowptr[n] = carry;
}

__global__ void copy_cursor_kernel(const int* __restrict__ rowptr, int* __restrict__ cur, int n)
{
    int i = blockIdx.x * blockDim.x + threadIdx.x;
    if (i < n) cur[i] = rowptr[i];
}

__global__ void fill_kernel(const int* __restrict__ src, const int* __restrict__ dst,
                            int E, int* __restrict__ cur, int* __restrict__ col)
{
    int e = blockIdx.x * blockDim.x + threadIdx.x;
    if (e < E) {
        int p = atomicAdd(&cur[dst[e]], 1);
        col[p] = src[e];
    }
}

// ---------------------------------------------------------------------------
// CSR mean aggregation (256 features; thread j = feature j)
// ---------------------------------------------------------------------------
__global__ __launch_bounds__(256)
void csr_mean_kernel(const int* __restrict__ rowptr, const int* __restrict__ col,
                     const float* __restrict__ feat, int ldf,
                     const float* __restrict__ add, int ldadd,
                     float* __restrict__ out, int relu)
{
    int node = blockIdx.x;
    int j = threadIdx.x;
    int s = rowptr[node], e = rowptr[node + 1];
    float acc = 0.f;
    int k = s;
    for (; k + 4 <= e; k += 4) {
        int c0 = col[k], c1 = col[k + 1], c2 = col[k + 2], c3 = col[k + 3];
        acc += (feat[(size_t)c0 * ldf + j] + feat[(size_t)c1 * ldf + j]) +
               (feat[(size_t)c2 * ldf + j] + feat[(size_t)c3 * ldf + j]);
    }
    for (; k < e; k++) acc += feat[(size_t)col[k] * ldf + j];
    float m = acc / fmaxf((float)(e - s), 1.f);
    if (add) m += add[(size_t)node * ldadd + j];
    if (relu) m = fmaxf(m, 0.f);
    out[(size_t)node * HID + j] = m;
}

// ---------------------------------------------------------------------------
// Host orchestration
// ---------------------------------------------------------------------------
static void launch_tf32(const float* A, int lda, const float* Bt, int ldb,
                        float* C, int ldc, float* C2, int splitcol, int ldc2,
                        const float* bias, const float* D, int ldd,
                        int M, int N, int K, int relu)
{
    dim3 grid(N / TBN, (M + TBM - 1) / TBM);
    size_t smem = (size_t)2 * STAGE_F * sizeof(float);
    tf32_gemm_kernel<<<grid, 256, smem>>>(A, lda, Bt, ldb, C, ldc, C2, splitcol, ldc2,
                                          bias, D, ldd, M, N, K, relu);
}

static void build_csr(const int* edges, int E, int* rowptr, int* cnt, int* col)
{
    const int* src = edges;
    const int* dst = edges + E;
    cudaMemsetAsync(cnt, 0, N_NODES * sizeof(int));
    hist_kernel<<<(E + 255) / 256, 256>>>(dst, E, cnt);
    exscan_kernel<<<1, 1024>>>(cnt, rowptr, N_NODES);
    copy_cursor_kernel<<<(N_NODES + 255) / 256, 256>>>(rowptr, cnt, N_NODES);
    fill_kernel<<<(E + 255) / 256, 256>>>(src, dst, E, cnt, col);
}

extern "C" void kernel_launch(void* const* d_in, const int* in_sizes, int n_in,
                              void* d_out, int out_size)
{
    const float* article_x   = (const float*)d_in[0];
    const float* community_x = (const float*)d_in[1];
    const int* e_wb  = (const int*)d_in[2];
    const int* e_mb  = (const int*)d_in[3];
    const int* e_int = (const int*)d_in[4];
    const float* W1 = (const float*)d_in[5];
    const float* b1 = (const float*)d_in[6];
    const float* W2 = (const float*)d_in[7];
    const float* b2 = (const float*)d_in[8];
    const float* Wl1 = (const float*)d_in[9];
    const float* bl1 = (const float*)d_in[10];
    const float* Wr1 = (const float*)d_in[11];
    const float* Wl2 = (const float*)d_in[12];
    const float* bl2 = (const float*)d_in[13];
    const float* Wr2 = (const float*)d_in[14];
    const float* Wl3 = (const float*)d_in[15];
    const float* bl3 = (const float*)d_in[16];
    const float* Wr3 = (const float*)d_in[17];
    const float* W3  = (const float*)d_in[18];
    const float* b3  = (const float*)d_in[19];

    const int E_wb  = in_sizes[2] / 2;
    const int E_mb  = in_sizes[3] / 2;
    const int E_int = in_sizes[4] / 2;

    // raise dynamic smem limit for the tf32 GEMM (idempotent, host-side)
    cudaFuncSetAttribute(tf32_gemm_kernel, cudaFuncAttributeMaxDynamicSharedMemorySize,
                         2 * STAGE_F * (int)sizeof(float));

    float *A1, *A2, *C1, *CR3, *h1, *M2, *h2, *g2, *h3;
    float *Wfa, *Wcc, *Wfa_t, *Wcc_t, *Wr2_t, *Wl3_t, *W3_t, *bfa, *bcc;
    int *rp0, *rp1, *rp2, *cnt, *col0, *col1, *col2;
    cudaGetSymbolAddress((void**)&A1, g_A1);
    cudaGetSymbolAddress((void**)&A2, g_A2);
    cudaGetSymbolAddress((void**)&C1, g_C1);
    cudaGetSymbolAddress((void**)&CR3, g_CR3);
    cudaGetSymbolAddress((void**)&h1, g_h1);
    cudaGetSymbolAddress((void**)&M2, g_M2);
    cudaGetSymbolAddress((void**)&h2, g_h2);
    cudaGetSymbolAddress((void**)&g2, g_g2);
    cudaGetSymbolAddress((void**)&h3, g_h3);
    cudaGetSymbolAddress((void**)&Wfa, g_Wfa);
    cudaGetSymbolAddress((void**)&Wcc, g_Wcc);
    cudaGetSymbolAddress((void**)&Wfa_t, g_Wfa_t);
    cudaGetSymbolAddress((void**)&Wcc_t, g_Wcc_t);
    cudaGetSymbolAddress((void**)&Wr2_t, g_Wr2_t);
    cudaGetSymbolAddress((void**)&Wl3_t, g_Wl3_t);
    cudaGetSymbolAddress((void**)&W3_t, g_W3_t);
    cudaGetSymbolAddress((void**)&bfa, g_bfa);
    cudaGetSymbolAddress((void**)&bcc, g_bcc);
    cudaGetSymbolAddress((void**)&rp0, g_rp0);
    cudaGetSymbolAddress((void**)&rp1, g_rp1);
    cudaGetSymbolAddress((void**)&rp2, g_rp2);
    cudaGetSymbolAddress((void**)&cnt, g_cnt);
    cudaGetSymbolAddress((void**)&col0, g_col0);
    cudaGetSymbolAddress((void**)&col1, g_col1);
    cudaGetSymbolAddress((void**)&col2, g_col2);

    // --- 1. weight folding (exact fp32) ---------------------------------
    {
        dim3 g(HID / BN, (F_IN + BM - 1) / BM);
        sgemm_kernel<<<dim3(2, 6), 256>>>(W1, PROJ, Wl1, HID, Wfa, 512, F_IN, HID, PROJ);
        sgemm_kernel<<<dim3(2, 6), 256>>>(W1, PROJ, Wl2, HID, Wfa + 256, 512, F_IN, HID, PROJ);
        sgemm_kernel<<<dim3(2, 6), 256>>>(W2, PROJ, Wr1, HID, Wcc, 512, F_IN, HID, PROJ);
        (void)g;
    }
    copy_wr3_kernel<<<(F_IN * HID + 255) / 256, 256>>>(Wr3, Wcc);
    fuse_bias_kernel<<<1, 256>>>(b1, Wl1, Wl2, b2, Wr1, bl1, bl3, bfa, bcc);

    // --- 2. transpose + tf32-round all B operands ------------------------
    transpose_cvt_kernel<<<dim3(512 / 32, F_IN / 32), dim3(32, 8)>>>(Wfa, F_IN, 512, Wfa_t);
    transpose_cvt_kernel<<<dim3(512 / 32, F_IN / 32), dim3(32, 8)>>>(Wcc, F_IN, 512, Wcc_t);
    transpose_cvt_kernel<<<dim3(HID / 32, HID / 32), dim3(32, 8)>>>(Wr2, HID, HID, Wr2_t);
    transpose_cvt_kernel<<<dim3(HID / 32, HID / 32), dim3(32, 8)>>>(Wl3, HID, HID, Wl3_t);
    transpose_cvt_kernel<<<dim3(OUT_D / 32, HID / 32), dim3(32, 8)>>>(W3, HID, OUT_D, W3_t);

    // --- 3. CSR builds ---------------------------------------------------
    build_csr(e_wb, E_wb, rp0, cnt, col0);
    build_csr(e_mb, E_mb, rp1, cnt, col1);
    build_csr(e_int, E_int, rp2, cnt, col2);

    // --- 4. big projections (tf32 tensor) --------------------------------
    // [A1 | A2] = article_x @ Wfa + bfa
    launch_tf32(article_x, F_IN, Wfa_t, F_IN, A1, HID, A2, 256, HID,
                bfa, nullptr, 0, N_NODES, 512, F_IN, 0);
    // [C1 (w/ bl1) | CR3 (w/ bl3)] = community_x @ Wcc + bcc
    launch_tf32(community_x, F_IN, Wcc_t, F_IN, C1, HID, CR3, 256, HID,
                bcc, nullptr, 0, N_NODES, 512, F_IN, 0);

    // --- 5. conv1: h1 = relu(mean_wb(A1) + C1) ---------------------------
    csr_mean_kernel<<<N_NODES, 256>>>(rp0, col0, A1, HID, C1, HID, h1, 1);

    // --- 6. conv2: h2 = relu(mean_mb(A2) + h1 @ Wr2 + bl2) ---------------
    csr_mean_kernel<<<N_NODES, 256>>>(rp1, col1, A2, HID, nullptr, 0, M2, 0);
    launch_tf32(h1, HID, Wr2_t, HID, h2, HID, nullptr, 1 << 30, 0,
                bl2, M2, HID, N_NODES, HID, HID, 1);

    // --- 7. conv3: h3 = relu(mean_int(h2 @ Wl3) + CR3) -------------------
    launch_tf32(h2, HID, Wl3_t, HID, g2, HID, nullptr, 1 << 30, 0,
                nullptr, nullptr, 0, N_NODES, HID, HID, 0);
    csr_mean_kernel<<<N_NODES, 256>>>(rp2, col2, g2, HID, CR3, HID, h3, 1);

    // --- 8. out = h3 @ W3 + b3 -------------------------------------------
    launch_tf32(h3, HID, W3_t, HID, (float*)d_out, OUT_D, nullptr, 1 << 30, 0,
                b3, nullptr, 0, N_NODES, OUT_D, HID, 0);
}